// round 11
// baseline (speedup 1.0000x reference)
#include <cuda_runtime.h>
#include <math.h>

#define NV 778
#define VP 784            // 8*98 verts, 392 pairs
#define NP 392            // vertex pairs
#define NJ 16
#define NCOMP 24
#define NBETA 10
#define FC 1554
#define NA 32
#define NB 8
#define NOBJ 16384

#define NCH 8
#define CPL 49            // pairs per chunk (8*49 = 392)

#define OFF_CMAP 0
#define OFF_PEN  (NB*NOBJ)
#define OFF_VERTS (OFF_PEN + 1)
#define OFF_CC   (OFF_VERTS + NB*NV*3)

// pair-interleaved vertex data:
//  g_vpA[p] = { X=(x0,x1), Y=(y0,y1) }   g_vpB[p] = { Z=(z0,z1), Wn=(wn0,wn1) }
//  wn = -0.5*|v|^2  (sentinel: x=y=z=0, wn=-1e30)
__device__ ulonglong2 g_vpA[NB * NP];
__device__ ulonglong2 g_vpB[NB * NP];
__device__ float  g_normals[NB * NV * 3];  // UNNORMALIZED (sign-only use)
__device__ float  g_A[NB * NJ * 12];       // skinning transforms
__device__ float  g_pf[NB * 135];          // pose features

__constant__ int c_parents[NJ] = {-1,0,1,2,0,4,5,0,7,8,0,10,11,0,13,14};

__device__ __forceinline__ unsigned long long pack2(float v) {
    unsigned long long r; unsigned u = __float_as_uint(v);
    asm("mov.b64 %0, {%1, %1};" : "=l"(r) : "r"(u));
    return r;
}
__device__ __forceinline__ void unpack2(unsigned long long v, float& lo, float& hi) {
    unsigned a, b;
    asm("mov.b64 {%0, %1}, %2;" : "=r"(a), "=r"(b) : "l"(v));
    lo = __uint_as_float(a); hi = __uint_as_float(b);
}
#define FMA2(d,a,b,c) asm("fma.rn.f32x2 %0, %1, %2, %3;" : "=l"(d) : "l"(a), "l"(b), "l"(c))

// ---------------------------------------------------------------------------
// prep: per-batch pose pipeline (grid NB, 256 thr)
// ---------------------------------------------------------------------------
__global__ void __launch_bounds__(256) prep_kernel(
    const float* __restrict__ hand_pose, const float* __restrict__ hand_beta,
    const float* __restrict__ pca, const float* __restrict__ v_template,
    const float* __restrict__ shapedirs, const float* __restrict__ J_reg,
    float* __restrict__ out)
{
    __shared__ float s_pose[32];
    __shared__ float s_beta[NBETA];
    __shared__ float s_full[48];
    __shared__ float s_R[NJ * 9];
    __shared__ float s_J[48];
    __shared__ float s_T[NJ * 12];
    __shared__ float s_vsh[NV * 3];

    const int b = blockIdx.x;
    const int tid = threadIdx.x;
    const int wid = tid >> 5, lane = tid & 31;

    if (tid < 30) s_pose[tid] = hand_pose[b * 30 + tid];
    if (tid >= 32 && tid < 32 + NBETA) s_beta[tid - 32] = hand_beta[b * NBETA + (tid - 32)];
    for (int i = tid; i < NV * 3; i += 256) g_normals[b * NV * 3 + i] = 0.f;
    if (b == 0 && tid == 0) out[OFF_PEN] = 0.f;
    __syncthreads();

    // full pose + v_shaped
    if (tid < 3) s_full[tid] = s_pose[3 + tid];
    if (tid >= 64 && tid < 64 + 45) {
        int p = tid - 64;
        float acc = 0.f;
        #pragma unroll
        for (int k = 0; k < NCOMP; k++) acc = fmaf(s_pose[6 + k], pca[k * 45 + p], acc);
        s_full[3 + p] = acc;
    }
    for (int i = tid; i < NV * 3; i += 256) {
        const float2* sd = (const float2*)shapedirs + i * 5;
        float2 d0 = sd[0], d1 = sd[1], d2 = sd[2], d3 = sd[3], d4 = sd[4];
        float acc = v_template[i];
        acc = fmaf(d0.x, s_beta[0], acc); acc = fmaf(d0.y, s_beta[1], acc);
        acc = fmaf(d1.x, s_beta[2], acc); acc = fmaf(d1.y, s_beta[3], acc);
        acc = fmaf(d2.x, s_beta[4], acc); acc = fmaf(d2.y, s_beta[5], acc);
        acc = fmaf(d3.x, s_beta[6], acc); acc = fmaf(d3.y, s_beta[7], acc);
        acc = fmaf(d4.x, s_beta[8], acc); acc = fmaf(d4.y, s_beta[9], acc);
        s_vsh[i] = acc;
    }
    __syncthreads();

    // rodrigues
    if (tid < NJ) {
        float rx = s_full[tid * 3 + 0], ry = s_full[tid * 3 + 1], rz = s_full[tid * 3 + 2];
        float th = sqrtf(rx * rx + ry * ry + rz * rz + 1e-16f);
        float inv = 1.f / th;
        float kx = rx * inv, ky = ry * inv, kz = rz * inv;
        float c, s;
        sincosf(th, &s, &c);
        float ic = 1.f - c;
        float* R = &s_R[tid * 9];
        R[0] = c + ic * kx * kx;       R[1] = -s * kz + ic * kx * ky; R[2] =  s * ky + ic * kx * kz;
        R[3] =  s * kz + ic * ky * kx; R[4] = c + ic * ky * ky;       R[5] = -s * kx + ic * ky * kz;
        R[6] = -s * ky + ic * kz * kx; R[7] =  s * kx + ic * kz * ky; R[8] = c + ic * kz * kz;
    }
    // J = J_reg @ v_shaped (warp-coop, 8 warps x 6 outputs)
    #pragma unroll
    for (int q = 0; q < 6; q++) {
        int o = wid + 8 * q;
        int j = o / 3, d = o % 3;
        const float* jr = J_reg + j * NV;
        float acc = 0.f;
        #pragma unroll
        for (int k = 0; k < 25; k++) {
            int v = lane + 32 * k;
            if (v < NV) acc = fmaf(jr[v], s_vsh[v * 3 + d], acc);
        }
        #pragma unroll
        for (int off = 16; off > 0; off >>= 1) acc += __shfl_xor_sync(0xffffffffu, acc, off);
        if (lane == 0) s_J[o] = acc;
    }
    __syncthreads();

    // pose features
    if (tid >= 64 && tid < 64 + 135) {
        int p = tid - 64;
        int e = p % 9;
        float diag = ((e == 0) | (e == 4) | (e == 8)) ? 1.f : 0.f;
        g_pf[b * 135 + p] = s_R[(1 + p / 9) * 9 + e] - diag;
    }

    // kinematic chain (warp 0, level-parallel)
    if (wid == 0 && lane < 16) {
        const int j = lane;
        const int p = c_parents[j];
        float L[12];
        #pragma unroll
        for (int e = 0; e < 9; e++) L[(e / 3) * 4 + (e % 3)] = s_R[j * 9 + e];
        float jx = s_J[j * 3 + 0], jy = s_J[j * 3 + 1], jz = s_J[j * 3 + 2];
        if (j == 0) { L[3] = jx; L[7] = jy; L[11] = jz; }
        else {
            L[3]  = jx - s_J[p * 3 + 0];
            L[7]  = jy - s_J[p * 3 + 1];
            L[11] = jz - s_J[p * 3 + 2];
        }
        const int depth = (j == 0) ? 0 : ((j - 1) % 3) + 1;
        if (depth == 0) {
            #pragma unroll
            for (int k = 0; k < 12; k++) s_T[k] = L[k];
        }
        __syncwarp(0xffffu);
        #pragma unroll
        for (int l = 1; l <= 3; l++) {
            if (depth == l) {
                float Tp[12];
                #pragma unroll
                for (int k = 0; k < 12; k++) Tp[k] = s_T[p * 12 + k];
                #pragma unroll
                for (int r = 0; r < 3; r++) {
                    #pragma unroll
                    for (int c2 = 0; c2 < 4; c2++) {
                        float acc = (c2 == 3) ? Tp[r * 4 + 3] : 0.f;
                        #pragma unroll
                        for (int k = 0; k < 3; k++) acc = fmaf(Tp[r * 4 + k], L[k * 4 + c2], acc);
                        s_T[j * 12 + r * 4 + c2] = acc;
                    }
                }
            }
            __syncwarp(0xffffu);
        }
        #pragma unroll
        for (int r = 0; r < 3; r++) {
            float r0 = s_T[j * 12 + r * 4 + 0], r1 = s_T[j * 12 + r * 4 + 1], r2 = s_T[j * 12 + r * 4 + 2];
            g_A[(b * NJ + j) * 12 + r * 4 + 0] = r0;
            g_A[(b * NJ + j) * 12 + r * 4 + 1] = r1;
            g_A[(b * NJ + j) * 12 + r * 4 + 2] = r2;
            g_A[(b * NJ + j) * 12 + r * 4 + 3] = s_T[j * 12 + r * 4 + 3] - (r0 * jx + r1 * jy + r2 * jz);
        }
    }
}

// ---------------------------------------------------------------------------
// vert: v_shaped + posedirs einsum + LBS. grid NB*16 (49 verts/block), 256 thr
// ---------------------------------------------------------------------------
__global__ void __launch_bounds__(256) vert_kernel(
    const float* __restrict__ v_template, const float* __restrict__ shapedirs,
    const float* __restrict__ posedirs, const float* __restrict__ lbs_w,
    const float* __restrict__ hand_pose, const float* __restrict__ hand_beta,
    float* __restrict__ out)
{
    __shared__ float s_A[NJ * 12];
    __shared__ float s_vp[49 * 3];
    __shared__ float s_beta[NBETA];

    const int b = blockIdx.x >> 4;
    const int chunk = blockIdx.x & 15;
    const int vbase = chunk * 49;
    const int tid = threadIdx.x;
    const int wid = tid >> 5, lane = tid & 31;

    if (tid < NJ * 12) s_A[tid] = g_A[b * NJ * 12 + tid];
    if (tid >= 192 && tid < 192 + NBETA) s_beta[tid - 192] = hand_beta[b * NBETA + (tid - 192)];
    __syncthreads();

    float pfr[5];
    #pragma unroll
    for (int jj = 0; jj < 5; jj++) {
        int p = lane + 32 * jj;
        pfr[jj] = (p < 135) ? g_pf[b * 135 + p] : 0.f;
    }

    for (int r = wid; r < 49 * 3; r += 8) {
        int row = vbase * 3 + r;
        if (row < NV * 3) {
            const float* pd = posedirs + row * 135;
            float a = pfr[0] * pd[lane];
            a = fmaf(pfr[1], pd[lane + 32], a);
            a = fmaf(pfr[2], pd[lane + 64], a);
            a = fmaf(pfr[3], pd[lane + 96], a);
            if (lane < 7) a = fmaf(pfr[4], pd[lane + 128], a);
            #pragma unroll
            for (int off = 16; off > 0; off >>= 1)
                a += __shfl_xor_sync(0xffffffffu, a, off);
            if (lane == 0) {
                const float* sd = shapedirs + row * NBETA;
                float base = v_template[row];
                #pragma unroll
                for (int k = 0; k < NBETA; k++) base = fmaf(sd[k], s_beta[k], base);
                s_vp[r] = base + a;
            }
        }
    }
    __syncthreads();

    if (tid < 49) {
        int v = vbase + tid;
        if (v < NV) {
            const float4* w4 = (const float4*)(lbs_w + v * NJ);
            float4 a0 = w4[0], a1 = w4[1], a2 = w4[2], a3 = w4[3];
            float wj[16] = {a0.x,a0.y,a0.z,a0.w, a1.x,a1.y,a1.z,a1.w,
                            a2.x,a2.y,a2.z,a2.w, a3.x,a3.y,a3.z,a3.w};
            float M[12];
            #pragma unroll
            for (int k = 0; k < 12; k++) M[k] = 0.f;
            #pragma unroll
            for (int j = 0; j < NJ; j++) {
                #pragma unroll
                for (int k = 0; k < 12; k++) M[k] = fmaf(wj[j], s_A[j * 12 + k], M[k]);
            }
            float x = s_vp[tid * 3 + 0], y = s_vp[tid * 3 + 1], z = s_vp[tid * 3 + 2];
            float px = fmaf(M[0], x, fmaf(M[1],  y, fmaf(M[2],  z, M[3])))  + hand_pose[b * 30 + 0];
            float py = fmaf(M[4], x, fmaf(M[5],  y, fmaf(M[6],  z, M[7])))  + hand_pose[b * 30 + 1];
            float pz = fmaf(M[8], x, fmaf(M[9],  y, fmaf(M[10], z, M[11]))) + hand_pose[b * 30 + 2];
            out[OFF_VERTS + (b * NV + v) * 3 + 0] = px;
            out[OFF_VERTS + (b * NV + v) * 3 + 1] = py;
            out[OFF_VERTS + (b * NV + v) * 3 + 2] = pz;
            int p = v >> 1, i = v & 1;
            float* A = (float*)&g_vpA[b * NP + p];
            float* B = (float*)&g_vpB[b * NP + p];
            A[i] = px; A[2 + i] = py;
            B[i] = pz; B[2 + i] = -0.5f * (px * px + py * py + pz * pz);
        } else if (v < VP) {
            int p = v >> 1, i = v & 1;
            float* A = (float*)&g_vpA[b * NP + p];
            float* B = (float*)&g_vpB[b * NP + p];
            A[i] = 0.f; A[2 + i] = 0.f;
            B[i] = 0.f; B[2 + i] = -1e30f;   // sentinel: never wins
        }
    }
}

// ---------------------------------------------------------------------------
// scatter: face-normal accumulation (global atomics) + contact candidates
// ---------------------------------------------------------------------------
__global__ void __launch_bounds__(256) scatter_kernel(
    const int* __restrict__ faces, const float* __restrict__ aw,
    const int* __restrict__ afi, float* __restrict__ out)
{
    const int tid = threadIdx.x;
    if (blockIdx.x < 49) {
        int i = blockIdx.x * 256 + tid;
        if (i >= NB * FC) return;
        int b = i / FC, f = i % FC;
        const float* vb = out + OFF_VERTS + b * NV * 3;
        int i0 = faces[f * 3 + 0], i1 = faces[f * 3 + 1], i2 = faces[f * 3 + 2];
        float p0x = vb[i0*3+0], p0y = vb[i0*3+1], p0z = vb[i0*3+2];
        float e1x = vb[i1*3+0]-p0x, e1y = vb[i1*3+1]-p0y, e1z = vb[i1*3+2]-p0z;
        float e2x = vb[i2*3+0]-p0x, e2y = vb[i2*3+1]-p0y, e2z = vb[i2*3+2]-p0z;
        float nx = e1y * e2z - e1z * e2y;
        float ny = e1z * e2x - e1x * e2z;
        float nz = e1x * e2y - e1y * e2x;
        float* gn = g_normals + b * NV * 3;
        atomicAdd(&gn[i0*3+0], nx); atomicAdd(&gn[i0*3+1], ny); atomicAdd(&gn[i0*3+2], nz);
        atomicAdd(&gn[i1*3+0], nx); atomicAdd(&gn[i1*3+1], ny); atomicAdd(&gn[i1*3+2], nz);
        atomicAdd(&gn[i2*3+0], nx); atomicAdd(&gn[i2*3+1], ny); atomicAdd(&gn[i2*3+2], nz);
    } else {
        for (int t = tid; t < NB * NA * 3; t += 256) {
            int b = t / (NA * 3);
            int r = t % (NA * 3);
            int a = r / 3, d = r % 3;
            const float* vb = out + OFF_VERTS + b * NV * 3;
            float acc = 0.f;
            #pragma unroll
            for (int k = 0; k < 3; k++)
                acc = fmaf(aw[a * 3 + k], vb[afi[a * 3 + k] * 3 + d], acc);
            out[OFF_CC + t] = acc;
        }
    }
}

// ---------------------------------------------------------------------------
// nn: fused NN + cmap + penetration. grid NB*64, 256 thr, 1 pt/thread
// packed f32x2 over vertex pairs: t = fma(X,OX, fma(Y,OY, fma(Z,OZ, Wn)))
// argmin d2 == argmax t ; d2 = |o|^2 - 2t
// ---------------------------------------------------------------------------
__global__ void __launch_bounds__(256) nn_kernel(const float* __restrict__ obj,
                                                 float* __restrict__ out)
{
    __shared__ ulonglong2 s_a[NP];
    __shared__ ulonglong2 s_b[NP];
    __shared__ float s_red[8];

    const int b = blockIdx.x >> 6;
    const int tile = blockIdx.x & 63;
    const int tid = threadIdx.x;

    for (int p = tid; p < NP; p += 256) {
        s_a[p] = g_vpA[b * NP + p];
        s_b[p] = g_vpB[b * NP + p];
    }
    __syncthreads();

    const int pt = tile * 256 + tid;
    const float* op = obj + (b * NOBJ + pt) * 3;
    const float ox = op[0], oy = op[1], oz = op[2];
    const unsigned long long OX = pack2(ox), OY = pack2(oy), OZ = pack2(oz);

    float me[NCH], mo[NCH];
    #pragma unroll
    for (int c = 0; c < NCH; c++) {
        const ulonglong2* pa = s_a + c * CPL;
        const ulonglong2* pb = s_b + c * CPL;
        float e = -3.4e38f, h = -3.4e38f;
        #pragma unroll 7
        for (int k = 0; k < CPL; k++) {
            ulonglong2 A = pa[k], B = pb[k];
            unsigned long long t;
            float lo, hi;
            FMA2(t, B.x, OZ, B.y);
            FMA2(t, A.y, OY, t);
            FMA2(t, A.x, OX, t);
            unpack2(t, lo, hi);
            e = fmaxf(e, lo); h = fmaxf(h, hi);
        }
        me[c] = e; mo[c] = h;
    }

    // merge chunk maxima (ascending order, strict > keeps first-argmin ties)
    float best = fmaxf(me[0], mo[0]); int bc = 0;
    #pragma unroll
    for (int c = 1; c < NCH; c++) {
        float cm = fmaxf(me[c], mo[c]);
        if (cm > best) { best = cm; bc = c; }
    }
    // exact in-order index recovery in winning chunk (even checked before odd)
    const float* fa = (const float*)(s_a + bc * CPL);
    const float* fb = (const float*)(s_b + bc * CPL);
    int idx = -1;
    for (int k = 0; k < CPL; k++) {
        float t0 = fmaf(fa[4*k+0], ox, fmaf(fa[4*k+2], oy, fmaf(fb[4*k+0], oz, fb[4*k+2])));
        float t1 = fmaf(fa[4*k+1], ox, fmaf(fa[4*k+3], oy, fmaf(fb[4*k+1], oz, fb[4*k+3])));
        if (idx < 0 && t0 == best) idx = 2 * k;
        if (idx < 0 && t1 == best) idx = 2 * k + 1;
    }
    const int bi = bc * (2 * CPL) + idx;

    float o2 = ox * ox + oy * oy + oz * oz;
    float d2 = fmaf(-2.f, best, o2);
    out[OFF_CMAP + b * NOBJ + pt] = 2.f / (1.f + __expf(100.f * d2));

    int pp = bi >> 1, ii = bi & 1;
    const float* Af = (const float*)&s_a[pp];
    const float* Bf = (const float*)&s_b[pp];
    float vx = Af[ii], vy = Af[2 + ii], vz = Bf[ii];
    const float* gn = g_normals + (b * NV + bi) * 3;
    float dp = (vx - ox) * gn[0] + (vy - oy) * gn[1] + (vz - oz) * gn[2];
    float pen = (dp > 0.f) ? d2 : 0.f;

    #pragma unroll
    for (int off = 16; off > 0; off >>= 1) pen += __shfl_down_sync(0xffffffffu, pen, off);
    if ((tid & 31) == 0) s_red[tid >> 5] = pen;
    __syncthreads();
    if (tid == 0) {
        float s = 0.f;
        #pragma unroll
        for (int w = 0; w < 8; w++) s += s_red[w];
        atomicAdd(&out[OFF_PEN], s * (1.f / NB));
    }
}

// ---------------------------------------------------------------------------
extern "C" void kernel_launch(void* const* d_in, const int* in_sizes, int n_in,
                              void* d_out, int out_size)
{
    const float* hand_pose  = (const float*)d_in[0];
    const float* obj_points = (const float*)d_in[1];
    const float* hand_beta  = (const float*)d_in[2];
    const float* v_template = (const float*)d_in[3];
    const float* shapedirs  = (const float*)d_in[4];
    const float* posedirs   = (const float*)d_in[5];
    const float* J_reg      = (const float*)d_in[6];
    const float* lbs_w      = (const float*)d_in[7];
    const float* pca        = (const float*)d_in[8];
    const float* aw         = (const float*)d_in[9];
    const int*   faces      = (const int*)d_in[10];
    const int*   afi        = (const int*)d_in[11];
    float* out = (float*)d_out;

    prep_kernel<<<NB, 256>>>(hand_pose, hand_beta, pca, v_template,
                             shapedirs, J_reg, out);
    vert_kernel<<<NB * 16, 256>>>(v_template, shapedirs, posedirs, lbs_w,
                                  hand_pose, hand_beta, out);
    scatter_kernel<<<50, 256>>>(faces, aw, afi, out);
    nn_kernel<<<NB * 64, 256>>>(obj_points, out);
}

// round 12
// speedup vs baseline: 1.1931x; 1.1931x over previous
#include <cuda_runtime.h>
#include <math.h>

#define NV 778
#define VP 784            // 8*98 verts, 392 pairs
#define NP 392            // vertex pairs
#define NJ 16
#define NCOMP 24
#define NBETA 10
#define FC 1554
#define NA 32
#define NB 8
#define NOBJ 16384

#define NCH 8
#define CPL 49            // pairs per chunk (8*49 = 392)

#define OFF_CMAP 0
#define OFF_PEN  (NB*NOBJ)
#define OFF_VERTS (OFF_PEN + 1)
#define OFF_CC   (OFF_VERTS + NB*NV*3)

// pair-interleaved vertex data:
//  g_vpA[p] = { X=(x0,x1), Y=(y0,y1) }   g_vpB[p] = { Z=(z0,z1), Wn=(wn0,wn1) }
//  wn = -0.5*|v|^2  (sentinel: x=y=z=0, wn=-1e30)
__device__ ulonglong2 g_vpA[NB * NP];
__device__ ulonglong2 g_vpB[NB * NP];
__device__ float  g_normals[NB * NV * 3];  // UNNORMALIZED (sign-only use)
__device__ float  g_A[NB * NJ * 12];       // skinning transforms
__device__ float  g_pf[NB * 135];          // pose features

__constant__ int c_parents[NJ] = {-1,0,1,2,0,4,5,0,7,8,0,10,11,0,13,14};

__device__ __forceinline__ unsigned long long pack2(float v) {
    unsigned long long r; unsigned u = __float_as_uint(v);
    asm("mov.b64 %0, {%1, %1};" : "=l"(r) : "r"(u));
    return r;
}
__device__ __forceinline__ void unpack2(unsigned long long v, float& lo, float& hi) {
    unsigned a, b;
    asm("mov.b64 {%0, %1}, %2;" : "=r"(a), "=r"(b) : "l"(v));
    lo = __uint_as_float(a); hi = __uint_as_float(b);
}
#define FMA2(d,a,b,c) asm("fma.rn.f32x2 %0, %1, %2, %3;" : "=l"(d) : "l"(a), "l"(b), "l"(c))

// ---------------------------------------------------------------------------
// prep: per-batch pose pipeline (grid NB, 256 thr)
// ---------------------------------------------------------------------------
__global__ void __launch_bounds__(256) prep_kernel(
    const float* __restrict__ hand_pose, const float* __restrict__ hand_beta,
    const float* __restrict__ pca, const float* __restrict__ v_template,
    const float* __restrict__ shapedirs, const float* __restrict__ J_reg,
    float* __restrict__ out)
{
    __shared__ float s_pose[32];
    __shared__ float s_beta[NBETA];
    __shared__ float s_full[48];
    __shared__ float s_R[NJ * 9];
    __shared__ float s_J[48];
    __shared__ float s_T[NJ * 12];
    __shared__ float s_vsh[NV * 3];

    const int b = blockIdx.x;
    const int tid = threadIdx.x;
    const int wid = tid >> 5, lane = tid & 31;

    if (tid < 30) s_pose[tid] = hand_pose[b * 30 + tid];
    if (tid >= 32 && tid < 32 + NBETA) s_beta[tid - 32] = hand_beta[b * NBETA + (tid - 32)];
    for (int i = tid; i < NV * 3; i += 256) g_normals[b * NV * 3 + i] = 0.f;
    if (b == 0 && tid == 0) out[OFF_PEN] = 0.f;
    __syncthreads();

    // full pose + v_shaped
    if (tid < 3) s_full[tid] = s_pose[3 + tid];
    if (tid >= 64 && tid < 64 + 45) {
        int p = tid - 64;
        float acc = 0.f;
        #pragma unroll
        for (int k = 0; k < NCOMP; k++) acc = fmaf(s_pose[6 + k], pca[k * 45 + p], acc);
        s_full[3 + p] = acc;
    }
    for (int i = tid; i < NV * 3; i += 256) {
        const float2* sd = (const float2*)shapedirs + i * 5;
        float2 d0 = sd[0], d1 = sd[1], d2 = sd[2], d3 = sd[3], d4 = sd[4];
        float acc = v_template[i];
        acc = fmaf(d0.x, s_beta[0], acc); acc = fmaf(d0.y, s_beta[1], acc);
        acc = fmaf(d1.x, s_beta[2], acc); acc = fmaf(d1.y, s_beta[3], acc);
        acc = fmaf(d2.x, s_beta[4], acc); acc = fmaf(d2.y, s_beta[5], acc);
        acc = fmaf(d3.x, s_beta[6], acc); acc = fmaf(d3.y, s_beta[7], acc);
        acc = fmaf(d4.x, s_beta[8], acc); acc = fmaf(d4.y, s_beta[9], acc);
        s_vsh[i] = acc;
    }
    __syncthreads();

    // rodrigues
    if (tid < NJ) {
        float rx = s_full[tid * 3 + 0], ry = s_full[tid * 3 + 1], rz = s_full[tid * 3 + 2];
        float th = sqrtf(rx * rx + ry * ry + rz * rz + 1e-16f);
        float inv = 1.f / th;
        float kx = rx * inv, ky = ry * inv, kz = rz * inv;
        float c, s;
        sincosf(th, &s, &c);
        float ic = 1.f - c;
        float* R = &s_R[tid * 9];
        R[0] = c + ic * kx * kx;       R[1] = -s * kz + ic * kx * ky; R[2] =  s * ky + ic * kx * kz;
        R[3] =  s * kz + ic * ky * kx; R[4] = c + ic * ky * ky;       R[5] = -s * kx + ic * ky * kz;
        R[6] = -s * ky + ic * kz * kx; R[7] =  s * kx + ic * kz * ky; R[8] = c + ic * kz * kz;
    }
    // J = J_reg @ v_shaped (warp-coop, 8 warps x 6 outputs)
    #pragma unroll
    for (int q = 0; q < 6; q++) {
        int o = wid + 8 * q;
        int j = o / 3, d = o % 3;
        const float* jr = J_reg + j * NV;
        float acc = 0.f;
        #pragma unroll
        for (int k = 0; k < 25; k++) {
            int v = lane + 32 * k;
            if (v < NV) acc = fmaf(jr[v], s_vsh[v * 3 + d], acc);
        }
        #pragma unroll
        for (int off = 16; off > 0; off >>= 1) acc += __shfl_xor_sync(0xffffffffu, acc, off);
        if (lane == 0) s_J[o] = acc;
    }
    __syncthreads();

    // pose features
    if (tid >= 64 && tid < 64 + 135) {
        int p = tid - 64;
        int e = p % 9;
        float diag = ((e == 0) | (e == 4) | (e == 8)) ? 1.f : 0.f;
        g_pf[b * 135 + p] = s_R[(1 + p / 9) * 9 + e] - diag;
    }

    // kinematic chain (warp 0, level-parallel)
    if (wid == 0 && lane < 16) {
        const int j = lane;
        const int p = c_parents[j];
        float L[12];
        #pragma unroll
        for (int e = 0; e < 9; e++) L[(e / 3) * 4 + (e % 3)] = s_R[j * 9 + e];
        float jx = s_J[j * 3 + 0], jy = s_J[j * 3 + 1], jz = s_J[j * 3 + 2];
        if (j == 0) { L[3] = jx; L[7] = jy; L[11] = jz; }
        else {
            L[3]  = jx - s_J[p * 3 + 0];
            L[7]  = jy - s_J[p * 3 + 1];
            L[11] = jz - s_J[p * 3 + 2];
        }
        const int depth = (j == 0) ? 0 : ((j - 1) % 3) + 1;
        if (depth == 0) {
            #pragma unroll
            for (int k = 0; k < 12; k++) s_T[k] = L[k];
        }
        __syncwarp(0xffffu);
        #pragma unroll
        for (int l = 1; l <= 3; l++) {
            if (depth == l) {
                float Tp[12];
                #pragma unroll
                for (int k = 0; k < 12; k++) Tp[k] = s_T[p * 12 + k];
                #pragma unroll
                for (int r = 0; r < 3; r++) {
                    #pragma unroll
                    for (int c2 = 0; c2 < 4; c2++) {
                        float acc = (c2 == 3) ? Tp[r * 4 + 3] : 0.f;
                        #pragma unroll
                        for (int k = 0; k < 3; k++) acc = fmaf(Tp[r * 4 + k], L[k * 4 + c2], acc);
                        s_T[j * 12 + r * 4 + c2] = acc;
                    }
                }
            }
            __syncwarp(0xffffu);
        }
        #pragma unroll
        for (int r = 0; r < 3; r++) {
            float r0 = s_T[j * 12 + r * 4 + 0], r1 = s_T[j * 12 + r * 4 + 1], r2 = s_T[j * 12 + r * 4 + 2];
            g_A[(b * NJ + j) * 12 + r * 4 + 0] = r0;
            g_A[(b * NJ + j) * 12 + r * 4 + 1] = r1;
            g_A[(b * NJ + j) * 12 + r * 4 + 2] = r2;
            g_A[(b * NJ + j) * 12 + r * 4 + 3] = s_T[j * 12 + r * 4 + 3] - (r0 * jx + r1 * jy + r2 * jz);
        }
    }
}

// ---------------------------------------------------------------------------
// vert: v_shaped + posedirs einsum + LBS. grid NB*16 (49 verts/block), 256 thr
// ---------------------------------------------------------------------------
__global__ void __launch_bounds__(256) vert_kernel(
    const float* __restrict__ v_template, const float* __restrict__ shapedirs,
    const float* __restrict__ posedirs, const float* __restrict__ lbs_w,
    const float* __restrict__ hand_pose, const float* __restrict__ hand_beta,
    float* __restrict__ out)
{
    __shared__ float s_A[NJ * 12];
    __shared__ float s_vp[49 * 3];
    __shared__ float s_beta[NBETA];

    const int b = blockIdx.x >> 4;
    const int chunk = blockIdx.x & 15;
    const int vbase = chunk * 49;
    const int tid = threadIdx.x;
    const int wid = tid >> 5, lane = tid & 31;

    if (tid < NJ * 12) s_A[tid] = g_A[b * NJ * 12 + tid];
    if (tid >= 192 && tid < 192 + NBETA) s_beta[tid - 192] = hand_beta[b * NBETA + (tid - 192)];
    __syncthreads();

    float pfr[5];
    #pragma unroll
    for (int jj = 0; jj < 5; jj++) {
        int p = lane + 32 * jj;
        pfr[jj] = (p < 135) ? g_pf[b * 135 + p] : 0.f;
    }

    for (int r = wid; r < 49 * 3; r += 8) {
        int row = vbase * 3 + r;
        if (row < NV * 3) {
            const float* pd = posedirs + row * 135;
            float a = pfr[0] * pd[lane];
            a = fmaf(pfr[1], pd[lane + 32], a);
            a = fmaf(pfr[2], pd[lane + 64], a);
            a = fmaf(pfr[3], pd[lane + 96], a);
            if (lane < 7) a = fmaf(pfr[4], pd[lane + 128], a);
            #pragma unroll
            for (int off = 16; off > 0; off >>= 1)
                a += __shfl_xor_sync(0xffffffffu, a, off);
            if (lane == 0) {
                const float* sd = shapedirs + row * NBETA;
                float base = v_template[row];
                #pragma unroll
                for (int k = 0; k < NBETA; k++) base = fmaf(sd[k], s_beta[k], base);
                s_vp[r] = base + a;
            }
        }
    }
    __syncthreads();

    if (tid < 49) {
        int v = vbase + tid;
        if (v < NV) {
            const float4* w4 = (const float4*)(lbs_w + v * NJ);
            float4 a0 = w4[0], a1 = w4[1], a2 = w4[2], a3 = w4[3];
            float wj[16] = {a0.x,a0.y,a0.z,a0.w, a1.x,a1.y,a1.z,a1.w,
                            a2.x,a2.y,a2.z,a2.w, a3.x,a3.y,a3.z,a3.w};
            float M[12];
            #pragma unroll
            for (int k = 0; k < 12; k++) M[k] = 0.f;
            #pragma unroll
            for (int j = 0; j < NJ; j++) {
                #pragma unroll
                for (int k = 0; k < 12; k++) M[k] = fmaf(wj[j], s_A[j * 12 + k], M[k]);
            }
            float x = s_vp[tid * 3 + 0], y = s_vp[tid * 3 + 1], z = s_vp[tid * 3 + 2];
            float px = fmaf(M[0], x, fmaf(M[1],  y, fmaf(M[2],  z, M[3])))  + hand_pose[b * 30 + 0];
            float py = fmaf(M[4], x, fmaf(M[5],  y, fmaf(M[6],  z, M[7])))  + hand_pose[b * 30 + 1];
            float pz = fmaf(M[8], x, fmaf(M[9],  y, fmaf(M[10], z, M[11]))) + hand_pose[b * 30 + 2];
            out[OFF_VERTS + (b * NV + v) * 3 + 0] = px;
            out[OFF_VERTS + (b * NV + v) * 3 + 1] = py;
            out[OFF_VERTS + (b * NV + v) * 3 + 2] = pz;
            int p = v >> 1, i = v & 1;
            float* A = (float*)&g_vpA[b * NP + p];
            float* B = (float*)&g_vpB[b * NP + p];
            A[i] = px; A[2 + i] = py;
            B[i] = pz; B[2 + i] = -0.5f * (px * px + py * py + pz * pz);
        } else if (v < VP) {
            int p = v >> 1, i = v & 1;
            float* A = (float*)&g_vpA[b * NP + p];
            float* B = (float*)&g_vpB[b * NP + p];
            A[i] = 0.f; A[2 + i] = 0.f;
            B[i] = 0.f; B[2 + i] = -1e30f;   // sentinel: never wins
        }
    }
}

// ---------------------------------------------------------------------------
// scatter: face-normal accumulation (global atomics) + contact candidates
// ---------------------------------------------------------------------------
__global__ void __launch_bounds__(256) scatter_kernel(
    const int* __restrict__ faces, const float* __restrict__ aw,
    const int* __restrict__ afi, float* __restrict__ out)
{
    const int tid = threadIdx.x;
    if (blockIdx.x < 49) {
        int i = blockIdx.x * 256 + tid;
        if (i >= NB * FC) return;
        int b = i / FC, f = i % FC;
        const float* vb = out + OFF_VERTS + b * NV * 3;
        int i0 = faces[f * 3 + 0], i1 = faces[f * 3 + 1], i2 = faces[f * 3 + 2];
        float p0x = vb[i0*3+0], p0y = vb[i0*3+1], p0z = vb[i0*3+2];
        float e1x = vb[i1*3+0]-p0x, e1y = vb[i1*3+1]-p0y, e1z = vb[i1*3+2]-p0z;
        float e2x = vb[i2*3+0]-p0x, e2y = vb[i2*3+1]-p0y, e2z = vb[i2*3+2]-p0z;
        float nx = e1y * e2z - e1z * e2y;
        float ny = e1z * e2x - e1x * e2z;
        float nz = e1x * e2y - e1y * e2x;
        float* gn = g_normals + b * NV * 3;
        atomicAdd(&gn[i0*3+0], nx); atomicAdd(&gn[i0*3+1], ny); atomicAdd(&gn[i0*3+2], nz);
        atomicAdd(&gn[i1*3+0], nx); atomicAdd(&gn[i1*3+1], ny); atomicAdd(&gn[i1*3+2], nz);
        atomicAdd(&gn[i2*3+0], nx); atomicAdd(&gn[i2*3+1], ny); atomicAdd(&gn[i2*3+2], nz);
    } else {
        for (int t = tid; t < NB * NA * 3; t += 256) {
            int b = t / (NA * 3);
            int r = t % (NA * 3);
            int a = r / 3, d = r % 3;
            const float* vb = out + OFF_VERTS + b * NV * 3;
            float acc = 0.f;
            #pragma unroll
            for (int k = 0; k < 3; k++)
                acc = fmaf(aw[a * 3 + k], vb[afi[a * 3 + k] * 3 + d], acc);
            out[OFF_CC + t] = acc;
        }
    }
}

// ---------------------------------------------------------------------------
// nn: fused NN + cmap + penetration.
// Lane-pair split: even lane computes chunks 0-3 for points (q0,q1),
// odd lane chunks 4-7 for the same 2 points; shfl_xor(1) merges; even lane
// finishes q0, odd finishes q1. grid NB*64, 256 thr (256 pts/block).
// packed f32x2: t = fma(X,OX, fma(Y,OY, fma(Z,OZ, Wn))) ; argmin d2 == argmax t
// ---------------------------------------------------------------------------
__global__ void __launch_bounds__(256) nn_kernel(const float* __restrict__ obj,
                                                 float* __restrict__ out)
{
    __shared__ ulonglong2 s_a[NP];
    __shared__ ulonglong2 s_b[NP];
    __shared__ float s_red[8];

    const int b = blockIdx.x >> 6;
    const int tile = blockIdx.x & 63;
    const int tid = threadIdx.x;
    const int parity = tid & 1;
    const int lp = tid >> 1;

    for (int p = tid; p < NP; p += 256) {
        s_a[p] = g_vpA[b * NP + p];
        s_b[p] = g_vpB[b * NP + p];
    }
    __syncthreads();

    const int q0 = tile * 256 + lp * 2;      // this lane-pair's two points
    const float* o0 = obj + (b * NOBJ + q0) * 3;
    const float ax = o0[0], ay = o0[1], az = o0[2];
    const float bx = o0[3], by = o0[4], bz = o0[5];
    const unsigned long long AX = pack2(ax), AY = pack2(ay), AZ = pack2(az);
    const unsigned long long BX = pack2(bx), BY = pack2(by), BZ = pack2(bz);

    // this thread's 4 chunks: parity 0 -> 0..3, parity 1 -> 4..7
    const ulonglong2* pa_base = s_a + parity * 4 * CPL;
    const ulonglong2* pb_base = s_b + parity * 4 * CPL;

    float meA[4], moA[4], meB[4], moB[4];
    #pragma unroll
    for (int c = 0; c < 4; c++) {
        const ulonglong2* pa = pa_base + c * CPL;
        const ulonglong2* pb = pb_base + c * CPL;
        float eA = -3.4e38f, hA = -3.4e38f, eB = -3.4e38f, hB = -3.4e38f;
        #pragma unroll 7
        for (int k = 0; k < CPL; k++) {
            ulonglong2 A = pa[k], B = pb[k];
            unsigned long long t;
            float lo, hi;
            FMA2(t, B.x, AZ, B.y);
            FMA2(t, A.y, AY, t);
            FMA2(t, A.x, AX, t);
            unpack2(t, lo, hi);
            eA = fmaxf(eA, lo); hA = fmaxf(hA, hi);
            FMA2(t, B.x, BZ, B.y);
            FMA2(t, A.y, BY, t);
            FMA2(t, A.x, BX, t);
            unpack2(t, lo, hi);
            eB = fmaxf(eB, lo); hB = fmaxf(hB, hi);
        }
        meA[c] = eA; moA[c] = hA; meB[c] = eB; moB[c] = hB;
    }

    // exchange: even sends its q1 data, odd sends its q0 data.
    // After: even lane owns q0's 8 chunk maxima; odd owns q1's.
    float cmax[8];
    #pragma unroll
    for (int c = 0; c < 4; c++) {
        float ownE = parity ? meB[c] : meA[c];   // my finish-point, my chunks
        float ownO = parity ? moB[c] : moA[c];
        float sndE = parity ? meA[c] : meB[c];   // partner's finish-point, my chunks
        float sndO = parity ? moA[c] : moB[c];
        float rcvE = __shfl_xor_sync(0xffffffffu, sndE, 1);
        float rcvO = __shfl_xor_sync(0xffffffffu, sndO, 1);
        float own = fmaxf(ownE, ownO);
        float rcv = fmaxf(rcvE, rcvO);
        // even lane: own chunks are 0-3 (low), received are 4-7 (high)
        // odd lane:  received are 0-3 (low), own are 4-7 (high)
        cmax[c]     = parity ? rcv : own;
        cmax[4 + c] = parity ? own : rcv;
    }

    // merge ascending (strict > keeps first-argmin ties)
    float best = cmax[0]; int bc = 0;
    #pragma unroll
    for (int c = 1; c < NCH; c++)
        if (cmax[c] > best) { best = cmax[c]; bc = c; }

    const float ox = parity ? bx : ax;
    const float oy = parity ? by : ay;
    const float oz = parity ? bz : az;
    const int pt = q0 + parity;

    // exact in-order index recovery in winning chunk (even vert before odd)
    const float* fa = (const float*)(s_a + bc * CPL);
    const float* fb = (const float*)(s_b + bc * CPL);
    int idx = -1;
    for (int k = 0; k < CPL; k++) {
        float t0 = fmaf(fa[4*k+0], ox, fmaf(fa[4*k+2], oy, fmaf(fb[4*k+0], oz, fb[4*k+2])));
        float t1 = fmaf(fa[4*k+1], ox, fmaf(fa[4*k+3], oy, fmaf(fb[4*k+1], oz, fb[4*k+3])));
        if (idx < 0 && t0 == best) idx = 2 * k;
        if (idx < 0 && t1 == best) idx = 2 * k + 1;
    }
    const int bi = bc * (2 * CPL) + idx;

    float o2 = ox * ox + oy * oy + oz * oz;
    float d2 = fmaf(-2.f, best, o2);
    out[OFF_CMAP + b * NOBJ + pt] = 2.f / (1.f + __expf(100.f * d2));

    int pp = bi >> 1, ii = bi & 1;
    const float* Af = (const float*)&s_a[pp];
    const float* Bf = (const float*)&s_b[pp];
    float vx = Af[ii], vy = Af[2 + ii], vz = Bf[ii];
    const float* gn = g_normals + (b * NV + bi) * 3;
    float dp = (vx - ox) * gn[0] + (vy - oy) * gn[1] + (vz - oz) * gn[2];
    float pen = (dp > 0.f) ? d2 : 0.f;

    #pragma unroll
    for (int off = 16; off > 0; off >>= 1) pen += __shfl_down_sync(0xffffffffu, pen, off);
    if ((tid & 31) == 0) s_red[tid >> 5] = pen;
    __syncthreads();
    if (tid == 0) {
        float s = 0.f;
        #pragma unroll
        for (int w = 0; w < 8; w++) s += s_red[w];
        atomicAdd(&out[OFF_PEN], s * (1.f / NB));
    }
}

// ---------------------------------------------------------------------------
extern "C" void kernel_launch(void* const* d_in, const int* in_sizes, int n_in,
                              void* d_out, int out_size)
{
    const float* hand_pose  = (const float*)d_in[0];
    const float* obj_points = (const float*)d_in[1];
    const float* hand_beta  = (const float*)d_in[2];
    const float* v_template = (const float*)d_in[3];
    const float* shapedirs  = (const float*)d_in[4];
    const float* posedirs   = (const float*)d_in[5];
    const float* J_reg      = (const float*)d_in[6];
    const float* lbs_w      = (const float*)d_in[7];
    const float* pca        = (const float*)d_in[8];
    const float* aw         = (const float*)d_in[9];
    const int*   faces      = (const int*)d_in[10];
    const int*   afi        = (const int*)d_in[11];
    float* out = (float*)d_out;

    prep_kernel<<<NB, 256>>>(hand_pose, hand_beta, pca, v_template,
                             shapedirs, J_reg, out);
    vert_kernel<<<NB * 16, 256>>>(v_template, shapedirs, posedirs, lbs_w,
                                  hand_pose, hand_beta, out);
    scatter_kernel<<<50, 256>>>(faces, aw, afi, out);
    nn_kernel<<<NB * 64, 256>>>(obj_points, out);
}

// round 13
// speedup vs baseline: 1.2769x; 1.0703x over previous
#include <cuda_runtime.h>
#include <math.h>

#define NV 778
#define VP 784            // 8*98 verts, 392 pairs
#define NP 392            // vertex pairs
#define NJ 16
#define NCOMP 24
#define NBETA 10
#define FC 1554
#define NA 32
#define NB 8
#define NOBJ 16384

#define NCH 8
#define CPL 49            // pairs per chunk (8*49 = 392)

#define OFF_CMAP 0
#define OFF_PEN  (NB*NOBJ)
#define OFF_VERTS (OFF_PEN + 1)
#define OFF_CC   (OFF_VERTS + NB*NV*3)

// pair-interleaved vertex data:
//  g_vpA[p] = { X=(x0,x1), Y=(y0,y1) }   g_vpB[p] = { Z=(z0,z1), Wn=(wn0,wn1) }
//  wn = -0.5*|v|^2  (sentinel: x=y=z=0, wn=-1e30)
__device__ ulonglong2 g_vpA[NB * NP];
__device__ ulonglong2 g_vpB[NB * NP];
__device__ float  g_normals[NB * NV * 3];  // UNNORMALIZED (sign-only use)
__device__ float  g_A[NB * NJ * 12];       // skinning transforms
__device__ float  g_pf[NB * 135];          // pose features

__constant__ int c_parents[NJ] = {-1,0,1,2,0,4,5,0,7,8,0,10,11,0,13,14};

__device__ __forceinline__ unsigned long long pack2(float v) {
    unsigned long long r; unsigned u = __float_as_uint(v);
    asm("mov.b64 %0, {%1, %1};" : "=l"(r) : "r"(u));
    return r;
}
__device__ __forceinline__ void unpack2(unsigned long long v, float& lo, float& hi) {
    unsigned a, b;
    asm("mov.b64 {%0, %1}, %2;" : "=r"(a), "=r"(b) : "l"(v));
    lo = __uint_as_float(a); hi = __uint_as_float(b);
}
#define FMA2(d,a,b,c) asm("fma.rn.f32x2 %0, %1, %2, %3;" : "=l"(d) : "l"(a), "l"(b), "l"(c))

// ---------------------------------------------------------------------------
// prep: per-batch pose pipeline (grid NB, 256 thr)
// ---------------------------------------------------------------------------
__global__ void __launch_bounds__(256) prep_kernel(
    const float* __restrict__ hand_pose, const float* __restrict__ hand_beta,
    const float* __restrict__ pca, const float* __restrict__ v_template,
    const float* __restrict__ shapedirs, const float* __restrict__ J_reg,
    float* __restrict__ out)
{
    __shared__ float s_pose[32];
    __shared__ float s_beta[NBETA];
    __shared__ float s_full[48];
    __shared__ float s_R[NJ * 9];
    __shared__ float s_J[48];
    __shared__ float s_T[NJ * 12];
    __shared__ float s_vsh[NV * 3];

    const int b = blockIdx.x;
    const int tid = threadIdx.x;
    const int wid = tid >> 5, lane = tid & 31;

    if (tid < 30) s_pose[tid] = hand_pose[b * 30 + tid];
    if (tid >= 32 && tid < 32 + NBETA) s_beta[tid - 32] = hand_beta[b * NBETA + (tid - 32)];
    for (int i = tid; i < NV * 3; i += 256) g_normals[b * NV * 3 + i] = 0.f;
    if (b == 0 && tid == 0) out[OFF_PEN] = 0.f;
    __syncthreads();

    // full pose + v_shaped
    if (tid < 3) s_full[tid] = s_pose[3 + tid];
    if (tid >= 64 && tid < 64 + 45) {
        int p = tid - 64;
        float acc = 0.f;
        #pragma unroll
        for (int k = 0; k < NCOMP; k++) acc = fmaf(s_pose[6 + k], pca[k * 45 + p], acc);
        s_full[3 + p] = acc;
    }
    for (int i = tid; i < NV * 3; i += 256) {
        const float2* sd = (const float2*)shapedirs + i * 5;
        float2 d0 = sd[0], d1 = sd[1], d2 = sd[2], d3 = sd[3], d4 = sd[4];
        float acc = v_template[i];
        acc = fmaf(d0.x, s_beta[0], acc); acc = fmaf(d0.y, s_beta[1], acc);
        acc = fmaf(d1.x, s_beta[2], acc); acc = fmaf(d1.y, s_beta[3], acc);
        acc = fmaf(d2.x, s_beta[4], acc); acc = fmaf(d2.y, s_beta[5], acc);
        acc = fmaf(d3.x, s_beta[6], acc); acc = fmaf(d3.y, s_beta[7], acc);
        acc = fmaf(d4.x, s_beta[8], acc); acc = fmaf(d4.y, s_beta[9], acc);
        s_vsh[i] = acc;
    }
    __syncthreads();

    // rodrigues
    if (tid < NJ) {
        float rx = s_full[tid * 3 + 0], ry = s_full[tid * 3 + 1], rz = s_full[tid * 3 + 2];
        float th = sqrtf(rx * rx + ry * ry + rz * rz + 1e-16f);
        float inv = 1.f / th;
        float kx = rx * inv, ky = ry * inv, kz = rz * inv;
        float c, s;
        sincosf(th, &s, &c);
        float ic = 1.f - c;
        float* R = &s_R[tid * 9];
        R[0] = c + ic * kx * kx;       R[1] = -s * kz + ic * kx * ky; R[2] =  s * ky + ic * kx * kz;
        R[3] =  s * kz + ic * ky * kx; R[4] = c + ic * ky * ky;       R[5] = -s * kx + ic * ky * kz;
        R[6] = -s * ky + ic * kz * kx; R[7] =  s * kx + ic * kz * ky; R[8] = c + ic * kz * kz;
    }
    // J = J_reg @ v_shaped (warp-coop, 8 warps x 6 outputs)
    #pragma unroll
    for (int q = 0; q < 6; q++) {
        int o = wid + 8 * q;
        int j = o / 3, d = o % 3;
        const float* jr = J_reg + j * NV;
        float acc = 0.f;
        #pragma unroll
        for (int k = 0; k < 25; k++) {
            int v = lane + 32 * k;
            if (v < NV) acc = fmaf(jr[v], s_vsh[v * 3 + d], acc);
        }
        #pragma unroll
        for (int off = 16; off > 0; off >>= 1) acc += __shfl_xor_sync(0xffffffffu, acc, off);
        if (lane == 0) s_J[o] = acc;
    }
    __syncthreads();

    // pose features
    if (tid >= 64 && tid < 64 + 135) {
        int p = tid - 64;
        int e = p % 9;
        float diag = ((e == 0) | (e == 4) | (e == 8)) ? 1.f : 0.f;
        g_pf[b * 135 + p] = s_R[(1 + p / 9) * 9 + e] - diag;
    }

    // kinematic chain (warp 0, level-parallel)
    if (wid == 0 && lane < 16) {
        const int j = lane;
        const int p = c_parents[j];
        float L[12];
        #pragma unroll
        for (int e = 0; e < 9; e++) L[(e / 3) * 4 + (e % 3)] = s_R[j * 9 + e];
        float jx = s_J[j * 3 + 0], jy = s_J[j * 3 + 1], jz = s_J[j * 3 + 2];
        if (j == 0) { L[3] = jx; L[7] = jy; L[11] = jz; }
        else {
            L[3]  = jx - s_J[p * 3 + 0];
            L[7]  = jy - s_J[p * 3 + 1];
            L[11] = jz - s_J[p * 3 + 2];
        }
        const int depth = (j == 0) ? 0 : ((j - 1) % 3) + 1;
        if (depth == 0) {
            #pragma unroll
            for (int k = 0; k < 12; k++) s_T[k] = L[k];
        }
        __syncwarp(0xffffu);
        #pragma unroll
        for (int l = 1; l <= 3; l++) {
            if (depth == l) {
                float Tp[12];
                #pragma unroll
                for (int k = 0; k < 12; k++) Tp[k] = s_T[p * 12 + k];
                #pragma unroll
                for (int r = 0; r < 3; r++) {
                    #pragma unroll
                    for (int c2 = 0; c2 < 4; c2++) {
                        float acc = (c2 == 3) ? Tp[r * 4 + 3] : 0.f;
                        #pragma unroll
                        for (int k = 0; k < 3; k++) acc = fmaf(Tp[r * 4 + k], L[k * 4 + c2], acc);
                        s_T[j * 12 + r * 4 + c2] = acc;
                    }
                }
            }
            __syncwarp(0xffffu);
        }
        #pragma unroll
        for (int r = 0; r < 3; r++) {
            float r0 = s_T[j * 12 + r * 4 + 0], r1 = s_T[j * 12 + r * 4 + 1], r2 = s_T[j * 12 + r * 4 + 2];
            g_A[(b * NJ + j) * 12 + r * 4 + 0] = r0;
            g_A[(b * NJ + j) * 12 + r * 4 + 1] = r1;
            g_A[(b * NJ + j) * 12 + r * 4 + 2] = r2;
            g_A[(b * NJ + j) * 12 + r * 4 + 3] = s_T[j * 12 + r * 4 + 3] - (r0 * jx + r1 * jy + r2 * jz);
        }
    }
}

// ---------------------------------------------------------------------------
// vert: v_shaped + posedirs einsum + LBS. grid NB*16 (49 verts/block), 256 thr
// ---------------------------------------------------------------------------
__global__ void __launch_bounds__(256) vert_kernel(
    const float* __restrict__ v_template, const float* __restrict__ shapedirs,
    const float* __restrict__ posedirs, const float* __restrict__ lbs_w,
    const float* __restrict__ hand_pose, const float* __restrict__ hand_beta,
    float* __restrict__ out)
{
    __shared__ float s_A[NJ * 12];
    __shared__ float s_vp[49 * 3];
    __shared__ float s_beta[NBETA];

    const int b = blockIdx.x >> 4;
    const int chunk = blockIdx.x & 15;
    const int vbase = chunk * 49;
    const int tid = threadIdx.x;
    const int wid = tid >> 5, lane = tid & 31;

    if (tid < NJ * 12) s_A[tid] = g_A[b * NJ * 12 + tid];
    if (tid >= 192 && tid < 192 + NBETA) s_beta[tid - 192] = hand_beta[b * NBETA + (tid - 192)];
    __syncthreads();

    float pfr[5];
    #pragma unroll
    for (int jj = 0; jj < 5; jj++) {
        int p = lane + 32 * jj;
        pfr[jj] = (p < 135) ? g_pf[b * 135 + p] : 0.f;
    }

    for (int r = wid; r < 49 * 3; r += 8) {
        int row = vbase * 3 + r;
        if (row < NV * 3) {
            const float* pd = posedirs + row * 135;
            float a = pfr[0] * pd[lane];
            a = fmaf(pfr[1], pd[lane + 32], a);
            a = fmaf(pfr[2], pd[lane + 64], a);
            a = fmaf(pfr[3], pd[lane + 96], a);
            if (lane < 7) a = fmaf(pfr[4], pd[lane + 128], a);
            #pragma unroll
            for (int off = 16; off > 0; off >>= 1)
                a += __shfl_xor_sync(0xffffffffu, a, off);
            if (lane == 0) {
                const float* sd = shapedirs + row * NBETA;
                float base = v_template[row];
                #pragma unroll
                for (int k = 0; k < NBETA; k++) base = fmaf(sd[k], s_beta[k], base);
                s_vp[r] = base + a;
            }
        }
    }
    __syncthreads();

    if (tid < 49) {
        int v = vbase + tid;
        if (v < NV) {
            const float4* w4 = (const float4*)(lbs_w + v * NJ);
            float4 a0 = w4[0], a1 = w4[1], a2 = w4[2], a3 = w4[3];
            float wj[16] = {a0.x,a0.y,a0.z,a0.w, a1.x,a1.y,a1.z,a1.w,
                            a2.x,a2.y,a2.z,a2.w, a3.x,a3.y,a3.z,a3.w};
            float M[12];
            #pragma unroll
            for (int k = 0; k < 12; k++) M[k] = 0.f;
            #pragma unroll
            for (int j = 0; j < NJ; j++) {
                #pragma unroll
                for (int k = 0; k < 12; k++) M[k] = fmaf(wj[j], s_A[j * 12 + k], M[k]);
            }
            float x = s_vp[tid * 3 + 0], y = s_vp[tid * 3 + 1], z = s_vp[tid * 3 + 2];
            float px = fmaf(M[0], x, fmaf(M[1],  y, fmaf(M[2],  z, M[3])))  + hand_pose[b * 30 + 0];
            float py = fmaf(M[4], x, fmaf(M[5],  y, fmaf(M[6],  z, M[7])))  + hand_pose[b * 30 + 1];
            float pz = fmaf(M[8], x, fmaf(M[9],  y, fmaf(M[10], z, M[11]))) + hand_pose[b * 30 + 2];
            out[OFF_VERTS + (b * NV + v) * 3 + 0] = px;
            out[OFF_VERTS + (b * NV + v) * 3 + 1] = py;
            out[OFF_VERTS + (b * NV + v) * 3 + 2] = pz;
            int p = v >> 1, i = v & 1;
            float* A = (float*)&g_vpA[b * NP + p];
            float* B = (float*)&g_vpB[b * NP + p];
            A[i] = px; A[2 + i] = py;
            B[i] = pz; B[2 + i] = -0.5f * (px * px + py * py + pz * pz);
        } else if (v < VP) {
            int p = v >> 1, i = v & 1;
            float* A = (float*)&g_vpA[b * NP + p];
            float* B = (float*)&g_vpB[b * NP + p];
            A[i] = 0.f; A[2 + i] = 0.f;
            B[i] = 0.f; B[2 + i] = -1e30f;   // sentinel: never wins
        }
    }
}

// ---------------------------------------------------------------------------
// scatter: face-normal accumulation (global atomics) + contact candidates
// ---------------------------------------------------------------------------
__global__ void __launch_bounds__(256) scatter_kernel(
    const int* __restrict__ faces, const float* __restrict__ aw,
    const int* __restrict__ afi, float* __restrict__ out)
{
    const int tid = threadIdx.x;
    if (blockIdx.x < 49) {
        int i = blockIdx.x * 256 + tid;
        if (i >= NB * FC) return;
        int b = i / FC, f = i % FC;
        const float* vb = out + OFF_VERTS + b * NV * 3;
        int i0 = faces[f * 3 + 0], i1 = faces[f * 3 + 1], i2 = faces[f * 3 + 2];
        float p0x = vb[i0*3+0], p0y = vb[i0*3+1], p0z = vb[i0*3+2];
        float e1x = vb[i1*3+0]-p0x, e1y = vb[i1*3+1]-p0y, e1z = vb[i1*3+2]-p0z;
        float e2x = vb[i2*3+0]-p0x, e2y = vb[i2*3+1]-p0y, e2z = vb[i2*3+2]-p0z;
        float nx = e1y * e2z - e1z * e2y;
        float ny = e1z * e2x - e1x * e2z;
        float nz = e1x * e2y - e1y * e2x;
        float* gn = g_normals + b * NV * 3;
        atomicAdd(&gn[i0*3+0], nx); atomicAdd(&gn[i0*3+1], ny); atomicAdd(&gn[i0*3+2], nz);
        atomicAdd(&gn[i1*3+0], nx); atomicAdd(&gn[i1*3+1], ny); atomicAdd(&gn[i1*3+2], nz);
        atomicAdd(&gn[i2*3+0], nx); atomicAdd(&gn[i2*3+1], ny); atomicAdd(&gn[i2*3+2], nz);
    } else {
        for (int t = tid; t < NB * NA * 3; t += 256) {
            int b = t / (NA * 3);
            int r = t % (NA * 3);
            int a = r / 3, d = r % 3;
            const float* vb = out + OFF_VERTS + b * NV * 3;
            float acc = 0.f;
            #pragma unroll
            for (int k = 0; k < 3; k++)
                acc = fmaf(aw[a * 3 + k], vb[afi[a * 3 + k] * 3 + d], acc);
            out[OFF_CC + t] = acc;
        }
    }
}

// ---------------------------------------------------------------------------
// nn: fused NN + cmap + penetration.
// 4-lane groups: lane g of a group owns vertex chunks {2g, 2g+1} and scans
// them for the group's 4 points; 2-round shfl butterfly merges (val, chunk)
// with first-chunk tie priority; lane g finishes point g.
// grid NB*128, 128 thr (128 pts/block). packed f32x2 math.
// argmin d2 == argmax t, t = o.v - 0.5|v|^2 ; d2 = |o|^2 - 2t
// ---------------------------------------------------------------------------
__global__ void __launch_bounds__(128) nn_kernel(const float* __restrict__ obj,
                                                 float* __restrict__ out)
{
    __shared__ ulonglong2 s_a[NP];
    __shared__ ulonglong2 s_b[NP];
    __shared__ float s_red[4];

    const int b = blockIdx.x >> 7;
    const int tile = blockIdx.x & 127;
    const int tid = threadIdx.x;
    const int g = tid & 3;         // lane within group of 4
    const int gq = tid >> 2;       // group id within block (0..31)

    for (int p = tid; p < NP; p += 128) {
        s_a[p] = g_vpA[b * NP + p];
        s_b[p] = g_vpB[b * NP + p];
    }
    __syncthreads();

    const int qbase = tile * 128 + gq * 4;   // group's 4 points
    // load 4 points (12 contiguous floats = 3 float4)
    const float4* o4 = (const float4*)(obj + (b * NOBJ + qbase) * 3);
    float4 f0 = o4[0], f1 = o4[1], f2 = o4[2];
    const unsigned long long X0 = pack2(f0.x), Y0 = pack2(f0.y), Z0 = pack2(f0.z);
    const unsigned long long X1 = pack2(f0.w), Y1 = pack2(f1.x), Z1 = pack2(f1.y);
    const unsigned long long X2 = pack2(f1.z), Y2 = pack2(f1.w), Z2 = pack2(f2.x);
    const unsigned long long X3 = pack2(f2.y), Y3 = pack2(f2.z), Z3 = pack2(f2.w);

    // per point, per own-chunk (2) maxima
    float cm[4][2];
    #pragma unroll
    for (int cc = 0; cc < 2; cc++) {
        const int chunk = 2 * g + cc;
        const ulonglong2* pa = s_a + chunk * CPL;
        const ulonglong2* pb = s_b + chunk * CPL;
        float e0 = -3.4e38f, h0 = -3.4e38f, e1 = -3.4e38f, h1 = -3.4e38f;
        float e2 = -3.4e38f, h2 = -3.4e38f, e3 = -3.4e38f, h3 = -3.4e38f;
        #pragma unroll 7
        for (int k = 0; k < CPL; k++) {
            ulonglong2 A = pa[k], B = pb[k];
            unsigned long long t; float lo, hi;
            FMA2(t, B.x, Z0, B.y); FMA2(t, A.y, Y0, t); FMA2(t, A.x, X0, t);
            unpack2(t, lo, hi); e0 = fmaxf(e0, lo); h0 = fmaxf(h0, hi);
            FMA2(t, B.x, Z1, B.y); FMA2(t, A.y, Y1, t); FMA2(t, A.x, X1, t);
            unpack2(t, lo, hi); e1 = fmaxf(e1, lo); h1 = fmaxf(h1, hi);
            FMA2(t, B.x, Z2, B.y); FMA2(t, A.y, Y2, t); FMA2(t, A.x, X2, t);
            unpack2(t, lo, hi); e2 = fmaxf(e2, lo); h2 = fmaxf(h2, hi);
            FMA2(t, B.x, Z3, B.y); FMA2(t, A.y, Y3, t); FMA2(t, A.x, X3, t);
            unpack2(t, lo, hi); e3 = fmaxf(e3, lo); h3 = fmaxf(h3, hi);
        }
        cm[0][cc] = fmaxf(e0, h0);
        cm[1][cc] = fmaxf(e1, h1);
        cm[2][cc] = fmaxf(e2, h2);
        cm[3][cc] = fmaxf(e3, h3);
    }

    // local best per point over own 2 chunks (lower chunk wins ties)
    float val[4]; int chk[4];
    #pragma unroll
    for (int p = 0; p < 4; p++) {
        if (cm[p][1] > cm[p][0]) { val[p] = cm[p][1]; chk[p] = 2 * g + 1; }
        else                     { val[p] = cm[p][0]; chk[p] = 2 * g; }
    }
    // butterfly merge across the 4 lanes (first-chunk priority on ties)
    #pragma unroll
    for (int m = 1; m <= 2; m <<= 1) {
        #pragma unroll
        for (int p = 0; p < 4; p++) {
            float ov = __shfl_xor_sync(0xffffffffu, val[p], m);
            int   oc = __shfl_xor_sync(0xffffffffu, chk[p], m);
            bool take = (ov > val[p]) || (ov == val[p] && oc < chk[p]);
            val[p] = take ? ov : val[p];
            chk[p] = take ? oc : chk[p];
        }
    }

    // lane g finishes point qbase+g
    const int pt = qbase + g;
    const float best = (g == 0) ? val[0] : (g == 1) ? val[1] : (g == 2) ? val[2] : val[3];
    const int bc     = (g == 0) ? chk[0] : (g == 1) ? chk[1] : (g == 2) ? chk[2] : chk[3];
    const float* op = obj + (b * NOBJ + pt) * 3;
    const float ox = op[0], oy = op[1], oz = op[2];

    // exact in-order index recovery in winning chunk (even vert before odd)
    const float* fa = (const float*)(s_a + bc * CPL);
    const float* fb = (const float*)(s_b + bc * CPL);
    int idx = -1;
    for (int k = 0; k < CPL; k++) {
        float t0 = fmaf(fa[4*k+0], ox, fmaf(fa[4*k+2], oy, fmaf(fb[4*k+0], oz, fb[4*k+2])));
        float t1 = fmaf(fa[4*k+1], ox, fmaf(fa[4*k+3], oy, fmaf(fb[4*k+1], oz, fb[4*k+3])));
        if (idx < 0 && t0 == best) idx = 2 * k;
        if (idx < 0 && t1 == best) idx = 2 * k + 1;
    }
    const int bi = bc * (2 * CPL) + idx;

    float o2 = ox * ox + oy * oy + oz * oz;
    float d2 = fmaf(-2.f, best, o2);
    out[OFF_CMAP + b * NOBJ + pt] = 2.f / (1.f + __expf(100.f * d2));

    int pp = bi >> 1, ii = bi & 1;
    const float* Af = (const float*)&s_a[pp];
    const float* Bf = (const float*)&s_b[pp];
    float vx = Af[ii], vy = Af[2 + ii], vz = Bf[ii];
    const float* gn = g_normals + (b * NV + bi) * 3;
    float dp = (vx - ox) * gn[0] + (vy - oy) * gn[1] + (vz - oz) * gn[2];
    float pen = (dp > 0.f) ? d2 : 0.f;

    #pragma unroll
    for (int off = 16; off > 0; off >>= 1) pen += __shfl_down_sync(0xffffffffu, pen, off);
    if ((tid & 31) == 0) s_red[tid >> 5] = pen;
    __syncthreads();
    if (tid == 0) {
        float s = s_red[0] + s_red[1] + s_red[2] + s_red[3];
        atomicAdd(&out[OFF_PEN], s * (1.f / NB));
    }
}

// ---------------------------------------------------------------------------
extern "C" void kernel_launch(void* const* d_in, const int* in_sizes, int n_in,
                              void* d_out, int out_size)
{
    const float* hand_pose  = (const float*)d_in[0];
    const float* obj_points = (const float*)d_in[1];
    const float* hand_beta  = (const float*)d_in[2];
    const float* v_template = (const float*)d_in[3];
    const float* shapedirs  = (const float*)d_in[4];
    const float* posedirs   = (const float*)d_in[5];
    const float* J_reg      = (const float*)d_in[6];
    const float* lbs_w      = (const float*)d_in[7];
    const float* pca        = (const float*)d_in[8];
    const float* aw         = (const float*)d_in[9];
    const int*   faces      = (const int*)d_in[10];
    const int*   afi        = (const int*)d_in[11];
    float* out = (float*)d_out;

    prep_kernel<<<NB, 256>>>(hand_pose, hand_beta, pca, v_template,
                             shapedirs, J_reg, out);
    vert_kernel<<<NB * 16, 256>>>(v_template, shapedirs, posedirs, lbs_w,
                                  hand_pose, hand_beta, out);
    scatter_kernel<<<50, 256>>>(faces, aw, afi, out);
    nn_kernel<<<NB * 128, 128>>>(obj_points, out);
}

// round 14
// speedup vs baseline: 1.3054x; 1.0223x over previous
#include <cuda_runtime.h>
#include <math.h>

#define NV 778
#define VP 784            // 8*98 verts, 392 pairs
#define NP 392            // vertex pairs
#define NJ 16
#define NCOMP 24
#define NBETA 10
#define FC 1554
#define NA 32
#define NB 8
#define NOBJ 16384

#define NCH 8
#define CPL 49            // pairs per chunk (8*49 = 392)

#define OFF_CMAP 0
#define OFF_PEN  (NB*NOBJ)
#define OFF_VERTS (OFF_PEN + 1)
#define OFF_CC   (OFF_VERTS + NB*NV*3)

// pair-interleaved vertex data:
//  g_vpA[p] = { X=(x0,x1), Y=(y0,y1) }   g_vpB[p] = { Z=(z0,z1), Wn=(wn0,wn1) }
//  wn = -0.5*|v|^2  (sentinel: x=y=z=0, wn=-1e30)
__device__ ulonglong2 g_vpA[NB * NP];
__device__ ulonglong2 g_vpB[NB * NP];
__device__ float  g_normals[NB * NV * 3];  // UNNORMALIZED (sign-only use)
__device__ float  g_JS[48 * NBETA];        // (J_reg @ shapedirs)[j,d,k]
__device__ float  g_JT[48];                // (J_reg @ v_template)[j,d]

__constant__ int c_parents[NJ] = {-1,0,1,2,0,4,5,0,7,8,0,10,11,0,13,14};

__device__ __forceinline__ unsigned long long pack2(float v) {
    unsigned long long r; unsigned u = __float_as_uint(v);
    asm("mov.b64 %0, {%1, %1};" : "=l"(r) : "r"(u));
    return r;
}
__device__ __forceinline__ void unpack2(unsigned long long v, float& lo, float& hi) {
    unsigned a, b;
    asm("mov.b64 {%0, %1}, %2;" : "=r"(a), "=r"(b) : "l"(v));
    lo = __uint_as_float(a); hi = __uint_as_float(b);
}
#define FMA2(d,a,b,c) asm("fma.rn.f32x2 %0, %1, %2, %3;" : "=l"(d) : "l"(a), "l"(b), "l"(c))

// ---------------------------------------------------------------------------
// jsjt: JS = J_reg@shapedirs, JT = J_reg@v_template (batch-independent)
// grid 48 (one block per (j,d)), 128 threads. Also zeroes normals + pen slot.
// ---------------------------------------------------------------------------
__global__ void __launch_bounds__(128) jsjt_kernel(
    const float* __restrict__ J_reg, const float* __restrict__ shapedirs,
    const float* __restrict__ v_template, float* __restrict__ out)
{
    const int o = blockIdx.x;           // 0..47
    const int j = o / 3, d = o % 3;
    const int tid = threadIdx.x;
    const int lane = tid & 31, wid = tid >> 5;
    __shared__ float s_red[4][11];

    // zero normals slice: 48 blocks cover NB*NV*3 = 18672 floats
    {
        const int per = (NB * NV * 3 + 47) / 48;   // 389
        int base = o * per;
        int end = base + per; if (end > NB * NV * 3) end = NB * NV * 3;
        for (int i = base + tid; i < end; i += 128) g_normals[i] = 0.f;
    }
    if (o == 0 && tid == 0) out[OFF_PEN] = 0.f;

    float acc[11];
    #pragma unroll
    for (int k = 0; k < 11; k++) acc[k] = 0.f;

    for (int v = tid; v < NV; v += 128) {
        float w = J_reg[j * NV + v];
        const float2* sd = (const float2*)(shapedirs + (v * 3 + d) * NBETA);
        float2 s0 = sd[0], s1 = sd[1], s2 = sd[2], s3 = sd[3], s4 = sd[4];
        acc[0] = fmaf(w, s0.x, acc[0]); acc[1] = fmaf(w, s0.y, acc[1]);
        acc[2] = fmaf(w, s1.x, acc[2]); acc[3] = fmaf(w, s1.y, acc[3]);
        acc[4] = fmaf(w, s2.x, acc[4]); acc[5] = fmaf(w, s2.y, acc[5]);
        acc[6] = fmaf(w, s3.x, acc[6]); acc[7] = fmaf(w, s3.y, acc[7]);
        acc[8] = fmaf(w, s4.x, acc[8]); acc[9] = fmaf(w, s4.y, acc[9]);
        acc[10] = fmaf(w, v_template[v * 3 + d], acc[10]);
    }
    #pragma unroll
    for (int k = 0; k < 11; k++) {
        #pragma unroll
        for (int off = 16; off > 0; off >>= 1)
            acc[k] += __shfl_xor_sync(0xffffffffu, acc[k], off);
    }
    if (lane == 0) {
        #pragma unroll
        for (int k = 0; k < 11; k++) s_red[wid][k] = acc[k];
    }
    __syncthreads();
    if (tid < 11) {
        float s = s_red[0][tid] + s_red[1][tid] + s_red[2][tid] + s_red[3][tid];
        if (tid < 10) g_JS[o * NBETA + tid] = s;
        else          g_JT[o] = s;
    }
}

// ---------------------------------------------------------------------------
// vert: full pose pipeline (redundant per block) + posedirs einsum + LBS.
// grid NB*16 (49 verts/block), 256 thr
// ---------------------------------------------------------------------------
__global__ void __launch_bounds__(256) vert_kernel(
    const float* __restrict__ v_template, const float* __restrict__ shapedirs,
    const float* __restrict__ posedirs, const float* __restrict__ lbs_w,
    const float* __restrict__ hand_pose, const float* __restrict__ hand_beta,
    const float* __restrict__ pca, float* __restrict__ out)
{
    __shared__ float s_pose[32];
    __shared__ float s_beta[NBETA];
    __shared__ float s_full[48];
    __shared__ float s_R[NJ * 9];
    __shared__ float s_J[48];
    __shared__ float s_T[NJ * 12];
    __shared__ float s_A[NJ * 12];
    __shared__ float s_pf[136];
    __shared__ float s_vp[49 * 3];

    const int b = blockIdx.x >> 4;
    const int chunk = blockIdx.x & 15;
    const int vbase = chunk * 49;
    const int tid = threadIdx.x;
    const int wid = tid >> 5, lane = tid & 31;

    if (tid < 30) s_pose[tid] = hand_pose[b * 30 + tid];
    if (tid >= 32 && tid < 32 + NBETA) s_beta[tid - 32] = hand_beta[b * NBETA + (tid - 32)];
    __syncthreads();

    // pca expansion -> full pose
    if (tid < 3) s_full[tid] = s_pose[3 + tid];
    if (tid >= 64 && tid < 64 + 45) {
        int p = tid - 64;
        float acc = 0.f;
        #pragma unroll
        for (int k = 0; k < NCOMP; k++) acc = fmaf(s_pose[6 + k], pca[k * 45 + p], acc);
        s_full[3 + p] = acc;
    }
    __syncthreads();

    // rodrigues (tid<16); J = JT + JS@beta (tid 192..239)
    if (tid < NJ) {
        float rx = s_full[tid * 3 + 0], ry = s_full[tid * 3 + 1], rz = s_full[tid * 3 + 2];
        float th = sqrtf(rx * rx + ry * ry + rz * rz + 1e-16f);
        float inv = 1.f / th;
        float kx = rx * inv, ky = ry * inv, kz = rz * inv;
        float c, s;
        sincosf(th, &s, &c);
        float ic = 1.f - c;
        float* R = &s_R[tid * 9];
        R[0] = c + ic * kx * kx;       R[1] = -s * kz + ic * kx * ky; R[2] =  s * ky + ic * kx * kz;
        R[3] =  s * kz + ic * ky * kx; R[4] = c + ic * ky * ky;       R[5] = -s * kx + ic * ky * kz;
        R[6] = -s * ky + ic * kz * kx; R[7] =  s * kx + ic * kz * ky; R[8] = c + ic * kz * kz;
    }
    if (tid >= 192 && tid < 240) {
        int o = tid - 192;
        float acc = g_JT[o];
        #pragma unroll
        for (int k = 0; k < NBETA; k++) acc = fmaf(g_JS[o * NBETA + k], s_beta[k], acc);
        s_J[o] = acc;
    }
    __syncthreads();

    // pose features (tids 64..198) ; kinematic chain (warp 0)
    if (tid >= 64 && tid < 64 + 135) {
        int p = tid - 64;
        int e = p % 9;
        float diag = ((e == 0) | (e == 4) | (e == 8)) ? 1.f : 0.f;
        s_pf[p] = s_R[(1 + p / 9) * 9 + e] - diag;
    }
    if (tid >= 199 && tid < 200) s_pf[135] = 0.f;
    if (wid == 0 && lane < 16) {
        const int j = lane;
        const int p = c_parents[j];
        float L[12];
        #pragma unroll
        for (int e = 0; e < 9; e++) L[(e / 3) * 4 + (e % 3)] = s_R[j * 9 + e];
        float jx = s_J[j * 3 + 0], jy = s_J[j * 3 + 1], jz = s_J[j * 3 + 2];
        if (j == 0) { L[3] = jx; L[7] = jy; L[11] = jz; }
        else {
            L[3]  = jx - s_J[p * 3 + 0];
            L[7]  = jy - s_J[p * 3 + 1];
            L[11] = jz - s_J[p * 3 + 2];
        }
        const int depth = (j == 0) ? 0 : ((j - 1) % 3) + 1;
        if (depth == 0) {
            #pragma unroll
            for (int k = 0; k < 12; k++) s_T[k] = L[k];
        }
        __syncwarp(0xffffu);
        #pragma unroll
        for (int l = 1; l <= 3; l++) {
            if (depth == l) {
                float Tp[12];
                #pragma unroll
                for (int k = 0; k < 12; k++) Tp[k] = s_T[p * 12 + k];
                #pragma unroll
                for (int r = 0; r < 3; r++) {
                    #pragma unroll
                    for (int c2 = 0; c2 < 4; c2++) {
                        float acc = (c2 == 3) ? Tp[r * 4 + 3] : 0.f;
                        #pragma unroll
                        for (int k = 0; k < 3; k++) acc = fmaf(Tp[r * 4 + k], L[k * 4 + c2], acc);
                        s_T[j * 12 + r * 4 + c2] = acc;
                    }
                }
            }
            __syncwarp(0xffffu);
        }
        #pragma unroll
        for (int r = 0; r < 3; r++) {
            float r0 = s_T[j * 12 + r * 4 + 0], r1 = s_T[j * 12 + r * 4 + 1], r2 = s_T[j * 12 + r * 4 + 2];
            s_A[j * 12 + r * 4 + 0] = r0;
            s_A[j * 12 + r * 4 + 1] = r1;
            s_A[j * 12 + r * 4 + 2] = r2;
            s_A[j * 12 + r * 4 + 3] = s_T[j * 12 + r * 4 + 3] - (r0 * jx + r1 * jy + r2 * jz);
        }
    }
    __syncthreads();

    // posedirs einsum (warp-cooperative rows)
    float pfr[5];
    #pragma unroll
    for (int jj = 0; jj < 5; jj++) {
        int p = lane + 32 * jj;
        pfr[jj] = (p < 135) ? s_pf[p] : 0.f;
    }
    for (int r = wid; r < 49 * 3; r += 8) {
        int row = vbase * 3 + r;
        if (row < NV * 3) {
            const float* pd = posedirs + row * 135;
            float a = pfr[0] * pd[lane];
            a = fmaf(pfr[1], pd[lane + 32], a);
            a = fmaf(pfr[2], pd[lane + 64], a);
            a = fmaf(pfr[3], pd[lane + 96], a);
            if (lane < 7) a = fmaf(pfr[4], pd[lane + 128], a);
            #pragma unroll
            for (int off = 16; off > 0; off >>= 1)
                a += __shfl_xor_sync(0xffffffffu, a, off);
            if (lane == 0) {
                const float* sd = shapedirs + row * NBETA;
                float base = v_template[row];
                #pragma unroll
                for (int k = 0; k < NBETA; k++) base = fmaf(sd[k], s_beta[k], base);
                s_vp[r] = base + a;
            }
        }
    }
    __syncthreads();

    // LBS for 49 verts
    if (tid < 49) {
        int v = vbase + tid;
        if (v < NV) {
            const float4* w4 = (const float4*)(lbs_w + v * NJ);
            float4 a0 = w4[0], a1 = w4[1], a2 = w4[2], a3 = w4[3];
            float wj[16] = {a0.x,a0.y,a0.z,a0.w, a1.x,a1.y,a1.z,a1.w,
                            a2.x,a2.y,a2.z,a2.w, a3.x,a3.y,a3.z,a3.w};
            float M[12];
            #pragma unroll
            for (int k = 0; k < 12; k++) M[k] = 0.f;
            #pragma unroll
            for (int j = 0; j < NJ; j++) {
                #pragma unroll
                for (int k = 0; k < 12; k++) M[k] = fmaf(wj[j], s_A[j * 12 + k], M[k]);
            }
            float x = s_vp[tid * 3 + 0], y = s_vp[tid * 3 + 1], z = s_vp[tid * 3 + 2];
            float px = fmaf(M[0], x, fmaf(M[1],  y, fmaf(M[2],  z, M[3])))  + s_pose[0];
            float py = fmaf(M[4], x, fmaf(M[5],  y, fmaf(M[6],  z, M[7])))  + s_pose[1];
            float pz = fmaf(M[8], x, fmaf(M[9],  y, fmaf(M[10], z, M[11]))) + s_pose[2];
            out[OFF_VERTS + (b * NV + v) * 3 + 0] = px;
            out[OFF_VERTS + (b * NV + v) * 3 + 1] = py;
            out[OFF_VERTS + (b * NV + v) * 3 + 2] = pz;
            int p = v >> 1, i = v & 1;
            float* A = (float*)&g_vpA[b * NP + p];
            float* B = (float*)&g_vpB[b * NP + p];
            A[i] = px; A[2 + i] = py;
            B[i] = pz; B[2 + i] = -0.5f * (px * px + py * py + pz * pz);
        } else if (v < VP) {
            int p = v >> 1, i = v & 1;
            float* A = (float*)&g_vpA[b * NP + p];
            float* B = (float*)&g_vpB[b * NP + p];
            A[i] = 0.f; A[2 + i] = 0.f;
            B[i] = 0.f; B[2 + i] = -1e30f;   // sentinel: never wins
        }
    }
}

// ---------------------------------------------------------------------------
// scatter: face-normal accumulation (global atomics) + contact candidates
// ---------------------------------------------------------------------------
__global__ void __launch_bounds__(256) scatter_kernel(
    const int* __restrict__ faces, const float* __restrict__ aw,
    const int* __restrict__ afi, float* __restrict__ out)
{
    const int tid = threadIdx.x;
    if (blockIdx.x < 49) {
        int i = blockIdx.x * 256 + tid;
        if (i >= NB * FC) return;
        int b = i / FC, f = i % FC;
        const float* vb = out + OFF_VERTS + b * NV * 3;
        int i0 = faces[f * 3 + 0], i1 = faces[f * 3 + 1], i2 = faces[f * 3 + 2];
        float p0x = vb[i0*3+0], p0y = vb[i0*3+1], p0z = vb[i0*3+2];
        float e1x = vb[i1*3+0]-p0x, e1y = vb[i1*3+1]-p0y, e1z = vb[i1*3+2]-p0z;
        float e2x = vb[i2*3+0]-p0x, e2y = vb[i2*3+1]-p0y, e2z = vb[i2*3+2]-p0z;
        float nx = e1y * e2z - e1z * e2y;
        float ny = e1z * e2x - e1x * e2z;
        float nz = e1x * e2y - e1y * e2x;
        float* gn = g_normals + b * NV * 3;
        atomicAdd(&gn[i0*3+0], nx); atomicAdd(&gn[i0*3+1], ny); atomicAdd(&gn[i0*3+2], nz);
        atomicAdd(&gn[i1*3+0], nx); atomicAdd(&gn[i1*3+1], ny); atomicAdd(&gn[i1*3+2], nz);
        atomicAdd(&gn[i2*3+0], nx); atomicAdd(&gn[i2*3+1], ny); atomicAdd(&gn[i2*3+2], nz);
    } else {
        for (int t = tid; t < NB * NA * 3; t += 256) {
            int b = t / (NA * 3);
            int r = t % (NA * 3);
            int a = r / 3, d = r % 3;
            const float* vb = out + OFF_VERTS + b * NV * 3;
            float acc = 0.f;
            #pragma unroll
            for (int k = 0; k < 3; k++)
                acc = fmaf(aw[a * 3 + k], vb[afi[a * 3 + k] * 3 + d], acc);
            out[OFF_CC + t] = acc;
        }
    }
}

// ---------------------------------------------------------------------------
// nn: fused NN + cmap + penetration.
// 4-lane groups: lane g owns vertex chunks {2g, 2g+1}, scans them for the
// group's 4 points; butterfly merge (val, chunk) with first-chunk tie
// priority; lane g finishes point g with vectorized exact recovery.
// grid NB*128, 128 thr. packed f32x2 math.
// argmin d2 == argmax t, t = o.v - 0.5|v|^2 ; d2 = |o|^2 - 2t
// ---------------------------------------------------------------------------
__global__ void __launch_bounds__(128) nn_kernel(const float* __restrict__ obj,
                                                 float* __restrict__ out)
{
    __shared__ ulonglong2 s_a[NP];
    __shared__ ulonglong2 s_b[NP];
    __shared__ float s_red[4];

    const int b = blockIdx.x >> 7;
    const int tile = blockIdx.x & 127;
    const int tid = threadIdx.x;
    const int g = tid & 3;         // lane within group of 4
    const int gq = tid >> 2;       // group id within block (0..31)

    for (int p = tid; p < NP; p += 128) {
        s_a[p] = g_vpA[b * NP + p];
        s_b[p] = g_vpB[b * NP + p];
    }
    __syncthreads();

    const int qbase = tile * 128 + gq * 4;   // group's 4 points
    const float4* o4 = (const float4*)(obj + (b * NOBJ + qbase) * 3);
    float4 f0 = o4[0], f1 = o4[1], f2 = o4[2];
    const unsigned long long X0 = pack2(f0.x), Y0 = pack2(f0.y), Z0 = pack2(f0.z);
    const unsigned long long X1 = pack2(f0.w), Y1 = pack2(f1.x), Z1 = pack2(f1.y);
    const unsigned long long X2 = pack2(f1.z), Y2 = pack2(f1.w), Z2 = pack2(f2.x);
    const unsigned long long X3 = pack2(f2.y), Y3 = pack2(f2.z), Z3 = pack2(f2.w);

    // per point, per own-chunk (2) maxima
    float cm[4][2];
    #pragma unroll
    for (int cc = 0; cc < 2; cc++) {
        const int chunk = 2 * g + cc;
        const ulonglong2* pa = s_a + chunk * CPL;
        const ulonglong2* pb = s_b + chunk * CPL;
        float e0 = -3.4e38f, h0 = -3.4e38f, e1 = -3.4e38f, h1 = -3.4e38f;
        float e2 = -3.4e38f, h2 = -3.4e38f, e3 = -3.4e38f, h3 = -3.4e38f;
        #pragma unroll 7
        for (int k = 0; k < CPL; k++) {
            ulonglong2 A = pa[k], B = pb[k];
            unsigned long long t; float lo, hi;
            FMA2(t, B.x, Z0, B.y); FMA2(t, A.y, Y0, t); FMA2(t, A.x, X0, t);
            unpack2(t, lo, hi); e0 = fmaxf(e0, lo); h0 = fmaxf(h0, hi);
            FMA2(t, B.x, Z1, B.y); FMA2(t, A.y, Y1, t); FMA2(t, A.x, X1, t);
            unpack2(t, lo, hi); e1 = fmaxf(e1, lo); h1 = fmaxf(h1, hi);
            FMA2(t, B.x, Z2, B.y); FMA2(t, A.y, Y2, t); FMA2(t, A.x, X2, t);
            unpack2(t, lo, hi); e2 = fmaxf(e2, lo); h2 = fmaxf(h2, hi);
            FMA2(t, B.x, Z3, B.y); FMA2(t, A.y, Y3, t); FMA2(t, A.x, X3, t);
            unpack2(t, lo, hi); e3 = fmaxf(e3, lo); h3 = fmaxf(h3, hi);
        }
        cm[0][cc] = fmaxf(e0, h0);
        cm[1][cc] = fmaxf(e1, h1);
        cm[2][cc] = fmaxf(e2, h2);
        cm[3][cc] = fmaxf(e3, h3);
    }

    // local best per point over own 2 chunks (lower chunk wins ties)
    float val[4]; int chk[4];
    #pragma unroll
    for (int p = 0; p < 4; p++) {
        if (cm[p][1] > cm[p][0]) { val[p] = cm[p][1]; chk[p] = 2 * g + 1; }
        else                     { val[p] = cm[p][0]; chk[p] = 2 * g; }
    }
    // butterfly merge across the 4 lanes (first-chunk priority on ties)
    #pragma unroll
    for (int m = 1; m <= 2; m <<= 1) {
        #pragma unroll
        for (int p = 0; p < 4; p++) {
            float ov = __shfl_xor_sync(0xffffffffu, val[p], m);
            int   oc = __shfl_xor_sync(0xffffffffu, chk[p], m);
            bool take = (ov > val[p]) || (ov == val[p] && oc < chk[p]);
            val[p] = take ? ov : val[p];
            chk[p] = take ? oc : chk[p];
        }
    }

    // lane g finishes point qbase+g
    const int pt = qbase + g;
    const float best = (g == 0) ? val[0] : (g == 1) ? val[1] : (g == 2) ? val[2] : val[3];
    const int bc     = (g == 0) ? chk[0] : (g == 1) ? chk[1] : (g == 2) ? chk[2] : chk[3];
    const float ox = (g == 0) ? f0.x : (g == 1) ? f0.w : (g == 2) ? f1.z : f2.y;
    const float oy = (g == 0) ? f0.y : (g == 1) ? f1.x : (g == 2) ? f1.w : f2.z;
    const float oz = (g == 0) ? f0.z : (g == 1) ? f1.y : (g == 2) ? f2.x : f2.w;

    // vectorized exact in-order index recovery (identical FMA2 chain as scan)
    const unsigned long long OX = pack2(ox), OY = pack2(oy), OZ = pack2(oz);
    const ulonglong2* ra = s_a + bc * CPL;
    const ulonglong2* rb = s_b + bc * CPL;
    int idx = -1;
    for (int k = 0; k < CPL; k++) {
        ulonglong2 A = ra[k], B = rb[k];
        unsigned long long t; float lo, hi;
        FMA2(t, B.x, OZ, B.y); FMA2(t, A.y, OY, t); FMA2(t, A.x, OX, t);
        unpack2(t, lo, hi);
        if (idx < 0 && lo == best) idx = 2 * k;
        if (idx < 0 && hi == best) idx = 2 * k + 1;
    }
    const int bi = bc * (2 * CPL) + idx;

    float o2 = ox * ox + oy * oy + oz * oz;
    float d2 = fmaf(-2.f, best, o2);
    out[OFF_CMAP + b * NOBJ + pt] = 2.f / (1.f + __expf(100.f * d2));

    int pp = bi >> 1, ii = bi & 1;
    const float* Af = (const float*)&s_a[pp];
    const float* Bf = (const float*)&s_b[pp];
    float vx = Af[ii], vy = Af[2 + ii], vz = Bf[ii];
    const float* gn = g_normals + (b * NV + bi) * 3;
    float dp = (vx - ox) * gn[0] + (vy - oy) * gn[1] + (vz - oz) * gn[2];
    float pen = (dp > 0.f) ? d2 : 0.f;

    #pragma unroll
    for (int off = 16; off > 0; off >>= 1) pen += __shfl_down_sync(0xffffffffu, pen, off);
    if ((tid & 31) == 0) s_red[tid >> 5] = pen;
    __syncthreads();
    if (tid == 0) {
        float s = s_red[0] + s_red[1] + s_red[2] + s_red[3];
        atomicAdd(&out[OFF_PEN], s * (1.f / NB));
    }
}

// ---------------------------------------------------------------------------
extern "C" void kernel_launch(void* const* d_in, const int* in_sizes, int n_in,
                              void* d_out, int out_size)
{
    const float* hand_pose  = (const float*)d_in[0];
    const float* obj_points = (const float*)d_in[1];
    const float* hand_beta  = (const float*)d_in[2];
    const float* v_template = (const float*)d_in[3];
    const float* shapedirs  = (const float*)d_in[4];
    const float* posedirs   = (const float*)d_in[5];
    const float* J_reg      = (const float*)d_in[6];
    const float* lbs_w      = (const float*)d_in[7];
    const float* pca        = (const float*)d_in[8];
    const float* aw         = (const float*)d_in[9];
    const int*   faces      = (const int*)d_in[10];
    const int*   afi        = (const int*)d_in[11];
    float* out = (float*)d_out;

    jsjt_kernel<<<48, 128>>>(J_reg, shapedirs, v_template, out);
    vert_kernel<<<NB * 16, 256>>>(v_template, shapedirs, posedirs, lbs_w,
                                  hand_pose, hand_beta, pca, out);
    scatter_kernel<<<50, 256>>>(faces, aw, afi, out);
    nn_kernel<<<NB * 128, 128>>>(obj_points, out);
}